// round 13
// baseline (speedup 1.0000x reference)
#include <cuda_runtime.h>

// Quanv layer, circuit collapsed to per-qubit Bloch components + Pauli strings:
//   out_q = cos(p_{3+q}) * <Z_q>_w  -  sin(p_{3+q}) * <X_q>_w
// One patch per thread (MLP_p1 = 1): per B300 spread model, front-batched
// multi-LDG threads at occ 8 cause cross-CTA L1tex queue contention
// (spr_max up to 2x); serial-load kernels sit at the 1.10 floor.
// MUFU trig (abs err ~5e-7, tol 1e-3).

__global__ __launch_bounds__(256, 8) void quanv_kernel(
    const float* __restrict__ x,      // [n, 4] angles
    const float* __restrict__ params, // [7]
    float* __restrict__ out,          // [n, 4]
    int n)
{
    int idx = blockIdx.x * blockDim.x + threadIdx.x;
    if (idx >= n) return;

    // Single patch load (one LDG.128 in flight during the param prologue).
    float4 a = ((const float4*)x)[idx];

    // Uniform param constants (broadcast loads + MUFU).
    float p0 = __ldg(params + 0);
    float p1 = __ldg(params + 1);
    float p2 = __ldg(params + 2);
    float p3 = __ldg(params + 3);
    float p4 = __ldg(params + 4);
    float p5 = __ldg(params + 5);
    float p6 = __ldg(params + 6);

    float Cp0 = __cosf(p0);
    float Cp2 = __cosf(p2);
    float C0 = __cosf(p3), S0 = __sinf(p3);
    float C1 = __cosf(p4), S1 = __sinf(p4);
    float C2 = __cosf(p5), S2 = __sinf(p5);
    float C3 = __cosf(p6), S3 = __sinf(p6);

    const float PI = 3.14159265358979323846f;

    // Per-qubit Bloch (x, z) after encoding RY(pi*a_q) + layer-1 gate.
    float t0 = a.x * PI;
    float x0 = __sinf(t0);              // RX leaves X
    float z0 = Cp0 * __cosf(t0);        // RX: z' = cos(p0) * z   (y = 0)

    float t1 = fmaf(a.y, PI, p1);       // RY(p1) adds angles
    float x1 = __sinf(t1);
    float z1 = __cosf(t1);

    float t2 = a.z * PI;
    float x2 = Cp2 * __sinf(t2);        // RZ: x' = cos(p2) * x
    float z2 = __cosf(t2);              // RZ leaves Z

    float t3 = a.w * PI;
    float x3 = __cosf(t3);              // H swaps X <-> Z
    float z3 = __sinf(t3);

    // Pauli strings after conjugating Z_q / X_q through the CNOT ring.
    float z01 = z0 * z1;
    float z23 = z2 * z3;
    float Z0w = z1 * z23;               // Z1 Z2 Z3
    float Z1w = z01;                    // Z0 Z1
    float Z2w = z01 * z2;               // Z0 Z1 Z2
    float Z3w = z01 * z23;              // Z0 Z1 Z2 Z3

    float x01 = x0 * x1;
    float X0w = x01;                    // X0 X1
    float X1w = x1 * x2;                // X1 X2
    float X2w = x2 * x3;                // X2 X3
    float X3w = x01 * x3;               // X0 X1 X3

    float4 o;
    o.x = fmaf(C0, Z0w, -S0 * X0w);
    o.y = fmaf(C1, Z1w, -S1 * X1w);
    o.z = fmaf(C2, Z2w, -S2 * X2w);
    o.w = fmaf(C3, Z3w, -S3 * X3w);
    ((float4*)out)[idx] = o;
}

extern "C" void kernel_launch(void* const* d_in, const int* in_sizes, int n_in,
                              void* d_out, int out_size)
{
    const float* x      = (const float*)d_in[0];   // [2048,3,196,4] fp32
    const float* params = (const float*)d_in[1];   // [7] fp32
    float* out = (float*)d_out;                    // flat [n,4] fp32

    int n = in_sizes[0] / 4;       // patches
    int threads = 256;
    int blocks = (n + threads - 1) / threads;
    quanv_kernel<<<blocks, threads>>>(x, params, out, n);
}

// round 14
// speedup vs baseline: 1.2362x; 1.2362x over previous
#include <cuda_runtime.h>

// Quanv layer, circuit collapsed to per-qubit Bloch components + Pauli strings:
//   out_q = cos(p_{3+q}) * <Z_q>_w  -  sin(p_{3+q}) * <X_q>_w
// Persistent software-pipelined kernel: 444 CTAs x 512 thr (148 SMs x 3,
// reg budget 42). Grid-stride, 2 patches/iter, next iteration's loads
// issued before current compute (register double-buffer) so the ~250-cyc
// L2 hit latency is hidden behind ~150 cyc of compute.
// MUFU trig (abs err ~5e-7, tol 1e-3).

__device__ __forceinline__ float4 quanv_one(
    float4 a, float Cp0, float p1, float Cp2,
    float4 C, float4 S)
{
    const float PI = 3.14159265358979323846f;

    // Per-qubit Bloch (x, z) after encoding RY(pi*a_q) + layer-1 gate.
    float t0 = a.x * PI;
    float x0 = __sinf(t0);              // RX leaves X
    float z0 = Cp0 * __cosf(t0);        // RX: z' = cos(p0) * z   (y = 0)

    float t1 = fmaf(a.y, PI, p1);       // RY(p1) adds angles
    float x1 = __sinf(t1);
    float z1 = __cosf(t1);

    float t2 = a.z * PI;
    float x2 = Cp2 * __sinf(t2);        // RZ: x' = cos(p2) * x
    float z2 = __cosf(t2);              // RZ leaves Z

    float t3 = a.w * PI;
    float x3 = __cosf(t3);              // H swaps X <-> Z
    float z3 = __sinf(t3);

    // Pauli strings after conjugating Z_q / X_q through the CNOT ring.
    float z01 = z0 * z1;
    float z23 = z2 * z3;
    float Z0w = z1 * z23;               // Z1 Z2 Z3
    float Z1w = z01;                    // Z0 Z1
    float Z2w = z01 * z2;               // Z0 Z1 Z2
    float Z3w = z01 * z23;              // Z0 Z1 Z2 Z3

    float x01 = x0 * x1;
    float X0w = x01;                    // X0 X1
    float X1w = x1 * x2;                // X1 X2
    float X2w = x2 * x3;                // X2 X3
    float X3w = x01 * x3;               // X0 X1 X3

    float4 o;
    o.x = fmaf(C.x, Z0w, -S.x * X0w);
    o.y = fmaf(C.y, Z1w, -S.y * X1w);
    o.z = fmaf(C.z, Z2w, -S.z * X2w);
    o.w = fmaf(C.w, Z3w, -S.w * X3w);
    return o;
}

__global__ __launch_bounds__(512, 3) void quanv_kernel(
    const float* __restrict__ x,      // [n, 4] angles
    const float* __restrict__ params, // [7]
    float* __restrict__ out,          // [n, 4]
    int n)
{
    const float4* xin = (const float4*)x;
    float4* xout = (float4*)out;

    int idx = blockIdx.x * blockDim.x + threadIdx.x;
    int T = gridDim.x * blockDim.x;

    // Prime the pipeline: first iteration's loads in flight during the
    // uniform param prologue.
    int i0 = idx;
    int j0 = i0 + T;
    bool v0i = (i0 < n);
    bool v0j = (j0 < n);
    float4 a0 = xin[v0i ? i0 : 0];
    float4 a1 = xin[v0j ? j0 : 0];

    // Uniform param constants (broadcast loads + MUFU), hoisted once.
    float p0 = __ldg(params + 0);
    float p1 = __ldg(params + 1);
    float p2 = __ldg(params + 2);
    float p3 = __ldg(params + 3);
    float p4 = __ldg(params + 4);
    float p5 = __ldg(params + 5);
    float p6 = __ldg(params + 6);

    float Cp0 = __cosf(p0);
    float Cp2 = __cosf(p2);
    float4 C, S;
    C.x = __cosf(p3); S.x = __sinf(p3);
    C.y = __cosf(p4); S.y = __sinf(p4);
    C.z = __cosf(p5); S.z = __sinf(p5);
    C.w = __cosf(p6); S.w = __sinf(p6);

    for (int i = i0; i < n; i += 2 * T) {
        int j = i + T;
        bool hasj = (j < n);

        // Prefetch next iteration (clamped -> always-valid address; the
        // loads are dead on the last iteration but harmless).
        int ni = i + 2 * T;
        int nj = ni + T;
        float4 b0 = xin[(ni < n) ? ni : 0];
        float4 b1 = xin[(nj < n) ? nj : 0];

        // Compute current two patches while b0/b1 are in flight.
        float4 o0 = quanv_one(a0, Cp0, p1, Cp2, C, S);
        xout[i] = o0;
        if (hasj) {
            float4 o1 = quanv_one(a1, Cp0, p1, Cp2, C, S);
            xout[j] = o1;
        }

        a0 = b0;
        a1 = b1;
    }
}

extern "C" void kernel_launch(void* const* d_in, const int* in_sizes, int n_in,
                              void* d_out, int out_size)
{
    const float* x      = (const float*)d_in[0];   // [2048,3,196,4] fp32
    const float* params = (const float*)d_in[1];   // [7] fp32
    float* out = (float*)d_out;                    // flat [n,4] fp32

    int n = in_sizes[0] / 4;       // patches
    int threads = 512;
    int blocks = 444;              // 148 SMs x 3 CTAs (reg budget 42)
    int maxBlocks = (n + threads - 1) / threads;
    if (blocks > maxBlocks) blocks = maxBlocks;
    if (blocks < 1) blocks = 1;
    quanv_kernel<<<blocks, threads>>>(x, params, out, n);
}